// round 5
// baseline (speedup 1.0000x reference)
#include <cuda_runtime.h>
#include <cuda_bf16.h>

// ---------------------------------------------------------------------------
// NDCG loss, N = 2^24.
// Pass 1 (k_count): read score, pack positivity bits into a global bitmask,
//                   write per-block positive counts.
// Pass 2 (k_main):  per-block exclusive prefix over block counts (+ total P),
//                   ballot-word based local scan, compute terms with FMA-only
//                   reciprocal / log2 (no MUFU in hot loop), per-block partial.
// Pass 3 (k_reduce): fixed-order final sum (double) -> scalar out.
// ---------------------------------------------------------------------------

#define CHUNK    8192
#define NTHREADS 256
#define NWARPS   (NTHREADS / 32)
#define MAX_WORDS  (1 << 20)   // supports n up to 2^25
#define MAX_BLOCKS 8192

__device__ unsigned g_mask[MAX_WORDS];
__device__ int      g_bcnt[MAX_BLOCKS];
__device__ float    g_partial[MAX_BLOCKS];

// FMA-only reciprocal: magic-constant seed + 3 Newton iterations.
// Seed rel err ~2.5e-3 -> 6e-6 -> ~4e-11; removes any systematic bias
// across the 2^24-term accumulation. Cost hidden under memory floor.
__device__ __forceinline__ float fastrcp(float x) {
    float r = __uint_as_float(0x7EF311C3u - __float_as_uint(x));
    r = r * fmaf(-x, r, 2.0f);
    r = r * fmaf(-x, r, 2.0f);
    r = r * fmaf(-x, r, 2.0f);
    return r;
}

// FMA-only log2: exponent extract + cubic minimax on mantissa in [1,2).
// p(1)=0, p(2)=1, max abs err ~4e-3 (only feeds the ~1e-7-weight s/l term).
__device__ __forceinline__ float log2a(float x) {
    int bits = __float_as_int(x);
    float e = (float)((bits >> 23) - 127);
    float m = __int_as_float((bits & 0x007FFFFF) | 0x3F800000);
    float lm = fmaf(fmaf(fmaf(0.1640425613f, m, -1.0988652862f), m,
                         3.1482979293f), m, -2.2134752044f);
    return e + lm;
}

__global__ __launch_bounds__(NTHREADS)
void k_count(const float* __restrict__ score, int n) {
    int tid  = threadIdx.x;
    int lane = tid & 31;
    int warp = tid >> 5;
    int base = blockIdx.x * CHUNK;
    int cnt = 0;
#pragma unroll
    for (int it = 0; it < CHUNK / NTHREADS; ++it) {
        int idx = base + it * NTHREADS + tid;
        float v = (idx < n) ? score[idx] : 0.0f;
        unsigned m = __ballot_sync(0xffffffffu, v > 0.0f);
        if (lane == 0) g_mask[idx >> 5] = m;
        cnt += __popc(m);   // all lanes hold the warp's running count
    }
    __shared__ int wc[NWARPS];
    if (lane == 0) wc[warp] = cnt;
    __syncthreads();
    if (tid == 0) {
        int s = 0;
#pragma unroll
        for (int i = 0; i < NWARPS; ++i) s += wc[i];
        g_bcnt[blockIdx.x] = s;
    }
}

__global__ __launch_bounds__(NTHREADS)
void k_main(const float* __restrict__ predict, int n, int nblocks) {
    int tid  = threadIdx.x;
    int lane = tid & 31;
    int warp = tid >> 5;
    int b    = blockIdx.x;

    // ---- phase 0: exclusive prefix of block counts + total P ----
    int pre = 0, tot = 0;
    for (int i = tid; i < nblocks; i += NTHREADS) {
        int c = g_bcnt[i];
        tot += c;
        if (i < b) pre += c;
    }
#pragma unroll
    for (int o = 16; o; o >>= 1) {
        pre += __shfl_down_sync(0xffffffffu, pre, o);
        tot += __shfl_down_sync(0xffffffffu, tot, o);
    }
    __shared__ int s_pre[NWARPS], s_tot[NWARPS];
    if (lane == 0) { s_pre[warp] = pre; s_tot[warp] = tot; }
    __syncthreads();

    __shared__ float s_sval, s_invsum;
    __shared__ int   s_P, s_K;
    if (tid == 0) {
        int P = 0, K = 0;
#pragma unroll
        for (int i = 0; i < NWARPS; ++i) { P += s_tot[i]; K += s_pre[i]; }
        float fS    = (float)P;          // S == P exactly (0/1 scores, P < 2^24)
        float sval  = 1.0f / fS;         // s at positive positions
        float sum_s = fS * sval;         // ~= jnp.sum(s)
        s_sval   = sval;
        s_invsum = 1.0f / sum_s;
        s_P = P;
        s_K = K;
    }
    __syncthreads();
    const float s_val     = s_sval;
    const float inv_sum_s = s_invsum;
    const int   P         = s_P;
    int kbase             = s_K;

    // ---- phase 1: this warp's 32 mask words + per-warp k offsets ----
    int base     = b * CHUNK;
    int wordBase = (base >> 5) + warp * 32;
    unsigned myword = g_mask[wordBase + lane];
    int wtot = __popc(myword);
#pragma unroll
    for (int o = 16; o; o >>= 1) wtot += __shfl_xor_sync(0xffffffffu, wtot, o);
    __shared__ int s_wc[NWARPS];
    if (lane == 0) s_wc[warp] = wtot;
    __syncthreads();
#pragma unroll
    for (int i = 0; i < NWARPS; ++i)
        if (i < warp) kbase += s_wc[i];

    // ---- phase 2: compute terms ----
    const unsigned le = 0xffffffffu >> (31 - lane);
    float acc = 0.0f;
    int idx0 = base + warp * (32 * 32) + lane;
#pragma unroll 8
    for (int it = 0; it < 32; ++it) {
        unsigned w = __shfl_sync(0xffffffffu, myword, it);
        int idx = idx0 + it * 32;
        float praw = (idx < n) ? __ldg(predict + idx) : 0.0f;
        float p = praw * inv_sum_s;
        int kinc = kbase + __popc(w & le);       // inclusive positive rank
        bool pos = (w >> lane) & 1u;

        float kp1 = (float)(kinc + 1);
        float l   = log2a(kp1);
        // negative-rank denominator: P + m + 1, m = idx+1-kinc
        float dng = (float)(P + idx + 2 - kinc);

        // pos:  t = (p*l - s*kp1) / (kp1*l)  ==  p/(k+1) - s/log2(k+1)
        // neg:  t = p / (P+m+1)
        float num = pos ? fmaf(-s_val, kp1, p * l) : p;
        float den = pos ? kp1 * l : dng;
        float t = num * fastrcp(den);
        acc = fmaf(t, t, acc);

        kbase += __popc(w);
    }

    // ---- block reduce ----
#pragma unroll
    for (int o = 16; o; o >>= 1) acc += __shfl_xor_sync(0xffffffffu, acc, o);
    __shared__ float s_acc[NWARPS];
    if (lane == 0) s_acc[warp] = acc;
    __syncthreads();
    if (tid == 0) {
        float s = 0.0f;
#pragma unroll
        for (int i = 0; i < NWARPS; ++i) s += s_acc[i];
        g_partial[b] = s;
    }
}

__global__ __launch_bounds__(256)
void k_reduce(float* __restrict__ out, int nblocks) {
    int tid = threadIdx.x;
    double s = 0.0;
    for (int i = tid; i < nblocks; i += 256) s += (double)g_partial[i];
#pragma unroll
    for (int o = 16; o; o >>= 1) s += __shfl_down_sync(0xffffffffu, s, o);
    __shared__ double sd[8];
    if ((tid & 31) == 0) sd[tid >> 5] = s;
    __syncthreads();
    if (tid == 0) {
        double t = 0.0;
#pragma unroll
        for (int i = 0; i < 8; ++i) t += sd[i];
        out[0] = (float)t;
    }
}

extern "C" void kernel_launch(void* const* d_in, const int* in_sizes, int n_in,
                              void* d_out, int out_size) {
    const float* predict = (const float*)d_in[0];
    const float* score   = (const float*)d_in[1];
    int n  = in_sizes[0];
    int nb = (n + CHUNK - 1) / CHUNK;
    if (nb > MAX_BLOCKS) nb = MAX_BLOCKS;  // (n fixed at 2^24 -> nb = 2048)

    k_count <<<nb, NTHREADS>>>(score, n);
    k_main  <<<nb, NTHREADS>>>(predict, n, nb);
    k_reduce<<<1, 256>>>((float*)d_out, nb);
}

// round 7
// speedup vs baseline: 1.2180x; 1.2180x over previous
#include <cuda_runtime.h>
#include <cuda_bf16.h>

// ---------------------------------------------------------------------------
// NDCG loss, N = 2^24.  float4 streaming + MUFU (LG2/RCP) math.
// Mask layout: per 128-element warp-tile, 4 words w0..w3; w_d holds the
// positivity bits of elements {tileBase + 4*t + d} at bit position t.
// ---------------------------------------------------------------------------

#define CHUNK    8192
#define NTHREADS 256
#define NWARPS   (NTHREADS / 32)
#define MAX_TILES  (1 << 18)   // n up to 2^25 (tiles of 128)
#define MAX_BLOCKS 8192

__device__ uint4 g_mask4[MAX_TILES];
__device__ int   g_bcnt[MAX_BLOCKS];
__device__ float g_partial[MAX_BLOCKS];

// ---------------------------------------------------------------------------
__global__ __launch_bounds__(NTHREADS)
void k_count(const float* __restrict__ score, int n) {
    int tid  = threadIdx.x;
    int lane = tid & 31;
    int warp = tid >> 5;
    int base = blockIdx.x * CHUNK;
    int warpBase = base + warp * 1024;     // 8 tiles of 128 per warp
    int cnt = 0;
#pragma unroll
    for (int j = 0; j < 8; ++j) {
        int tbase = warpBase + j * 128;
        int myIdx = tbase + lane * 4;
        float4 v;
        if (tbase + 128 <= n) {
            v = *reinterpret_cast<const float4*>(score + myIdx);
        } else {
            v.x = (myIdx + 0 < n) ? score[myIdx + 0] : 0.0f;
            v.y = (myIdx + 1 < n) ? score[myIdx + 1] : 0.0f;
            v.z = (myIdx + 2 < n) ? score[myIdx + 2] : 0.0f;
            v.w = (myIdx + 3 < n) ? score[myIdx + 3] : 0.0f;
        }
        unsigned w0 = __ballot_sync(0xffffffffu, v.x > 0.0f);
        unsigned w1 = __ballot_sync(0xffffffffu, v.y > 0.0f);
        unsigned w2 = __ballot_sync(0xffffffffu, v.z > 0.0f);
        unsigned w3 = __ballot_sync(0xffffffffu, v.w > 0.0f);
        if (lane == 0) g_mask4[tbase >> 7] = make_uint4(w0, w1, w2, w3);
        cnt += __popc(w0) + __popc(w1) + __popc(w2) + __popc(w3);
    }
    __shared__ int wc[NWARPS];
    if (lane == 0) wc[warp] = cnt;
    __syncthreads();
    if (tid == 0) {
        int s = 0;
#pragma unroll
        for (int i = 0; i < NWARPS; ++i) s += wc[i];
        g_bcnt[blockIdx.x] = s;
    }
}

// ---------------------------------------------------------------------------
// Per-element term.  pos: (p/(k+1) - s/log2(k+1))^2  via
//   num = p*l - s*(k+1), den = (k+1)*l, t = num/den.
// neg: (p/(P+m+1))^2 with m = idx+1-kinc.
// MUFU: 1x LG2 + 1x RCP per element; one I2F (int select first).
__device__ __forceinline__ float term(float praw, int kinc, int pos, int idx,
                                      float inv_sum_s, float s_val, int P) {
    float p  = praw * inv_sum_s;
    int   di = pos ? (kinc + 1) : (P + idx + 2 - kinc);
    float fd = (float)di;
    float l  = __log2f(fd);                 // lg2.approx (MUFU)
    float num = pos ? fmaf(-s_val, fd, p * l) : p;
    float den = pos ? fd * l : fd;
    return __fdividef(num, den);            // rcp.approx (MUFU) + mul
}

__global__ __launch_bounds__(NTHREADS)
void k_main(const float* __restrict__ predict, int n, int nblocks) {
    int tid  = threadIdx.x;
    int lane = tid & 31;
    int warp = tid >> 5;
    int b    = blockIdx.x;

    // ---- phase 0: exclusive prefix of block counts + total P ----
    int pre = 0, tot = 0;
    for (int i = tid; i < nblocks; i += NTHREADS) {
        int c = g_bcnt[i];
        tot += c;
        if (i < b) pre += c;
    }
#pragma unroll
    for (int o = 16; o; o >>= 1) {
        pre += __shfl_down_sync(0xffffffffu, pre, o);
        tot += __shfl_down_sync(0xffffffffu, tot, o);
    }
    __shared__ int s_pre[NWARPS], s_tot[NWARPS];
    if (lane == 0) { s_pre[warp] = pre; s_tot[warp] = tot; }
    __syncthreads();

    __shared__ float s_sval, s_invsum;
    __shared__ int   s_P, s_K;
    if (tid == 0) {
        int P = 0, K = 0;
#pragma unroll
        for (int i = 0; i < NWARPS; ++i) { P += s_tot[i]; K += s_pre[i]; }
        float fS    = (float)P;          // S == P exactly (0/1 scores, P < 2^24)
        float sval  = 1.0f / fS;
        float sum_s = fS * sval;         // ~= jnp.sum(s)
        s_sval   = sval;
        s_invsum = 1.0f / sum_s;
        s_P = P;
        s_K = K;
    }
    __syncthreads();
    const float s_val     = s_sval;
    const float inv_sum_s = s_invsum;
    const int   P         = s_P;
    int kbase             = s_K;

    // ---- phase 1: warp's 32 mask words (8 tiles x 4) + per-warp k offsets ----
    int base     = b * CHUNK;
    int warpBase = base + warp * 1024;
    const unsigned* g_words = reinterpret_cast<const unsigned*>(g_mask4);
    int wordBase = (base >> 5) + warp * 32;      // == (warpBase>>7)*4
    unsigned myword = g_words[wordBase + lane];
    int wtot = __popc(myword);
#pragma unroll
    for (int o = 16; o; o >>= 1) wtot += __shfl_xor_sync(0xffffffffu, wtot, o);
    __shared__ int s_wc[NWARPS];
    if (lane == 0) s_wc[warp] = wtot;
    __syncthreads();
#pragma unroll
    for (int i = 0; i < NWARPS; ++i)
        if (i < warp) kbase += s_wc[i];

    // ---- phase 2: compute terms, 128 elements per warp-iter ----
    const unsigned lt = (1u << lane) - 1u;       // lanes strictly below
    float acc = 0.0f;
#pragma unroll
    for (int j = 0; j < 8; ++j) {
        unsigned w0 = __shfl_sync(0xffffffffu, myword, 4 * j + 0);
        unsigned w1 = __shfl_sync(0xffffffffu, myword, 4 * j + 1);
        unsigned w2 = __shfl_sync(0xffffffffu, myword, 4 * j + 2);
        unsigned w3 = __shfl_sync(0xffffffffu, myword, 4 * j + 3);
        int tbase = warpBase + j * 128;
        int myIdx = tbase + lane * 4;
        float4 pv;
        if (tbase + 128 <= n) {
            pv = *reinterpret_cast<const float4*>(predict + myIdx);
        } else {
            pv.x = (myIdx + 0 < n) ? predict[myIdx + 0] : 0.0f;
            pv.y = (myIdx + 1 < n) ? predict[myIdx + 1] : 0.0f;
            pv.z = (myIdx + 2 < n) ? predict[myIdx + 2] : 0.0f;
            pv.w = (myIdx + 3 < n) ? predict[myIdx + 3] : 0.0f;
        }
        // exclusive positive count before this thread's 4 elements
        int pre4 = __popc(w0 & lt) + __popc(w1 & lt)
                 + __popc(w2 & lt) + __popc(w3 & lt);
        int b0 = (w0 >> lane) & 1;
        int b1 = (w1 >> lane) & 1;
        int b2 = (w2 >> lane) & 1;
        int b3 = (w3 >> lane) & 1;
        int k0 = kbase + pre4 + b0;   // inclusive rank at c=0
        int k1 = k0 + b1;
        int k2 = k1 + b2;
        int k3 = k2 + b3;
        float t0 = term(pv.x, k0, b0, myIdx + 0, inv_sum_s, s_val, P);
        float t1 = term(pv.y, k1, b1, myIdx + 1, inv_sum_s, s_val, P);
        float t2 = term(pv.z, k2, b2, myIdx + 2, inv_sum_s, s_val, P);
        float t3 = term(pv.w, k3, b3, myIdx + 3, inv_sum_s, s_val, P);
        acc = fmaf(t0, t0, acc);
        acc = fmaf(t1, t1, acc);
        acc = fmaf(t2, t2, acc);
        acc = fmaf(t3, t3, acc);
        kbase += __popc(w0) + __popc(w1) + __popc(w2) + __popc(w3);
    }

    // ---- block reduce ----
#pragma unroll
    for (int o = 16; o; o >>= 1) acc += __shfl_xor_sync(0xffffffffu, acc, o);
    __shared__ float s_acc[NWARPS];
    if (lane == 0) s_acc[warp] = acc;
    __syncthreads();
    if (tid == 0) {
        float s = 0.0f;
#pragma unroll
        for (int i = 0; i < NWARPS; ++i) s += s_acc[i];
        g_partial[b] = s;
    }
}

__global__ __launch_bounds__(256)
void k_reduce(float* __restrict__ out, int nblocks) {
    int tid = threadIdx.x;
    double s = 0.0;
    for (int i = tid; i < nblocks; i += 256) s += (double)g_partial[i];
#pragma unroll
    for (int o = 16; o; o >>= 1) s += __shfl_down_sync(0xffffffffu, s, o);
    __shared__ double sd[8];
    if ((tid & 31) == 0) sd[tid >> 5] = s;
    __syncthreads();
    if (tid == 0) {
        double t = 0.0;
#pragma unroll
        for (int i = 0; i < 8; ++i) t += sd[i];
        out[0] = (float)t;
    }
}

extern "C" void kernel_launch(void* const* d_in, const int* in_sizes, int n_in,
                              void* d_out, int out_size) {
    const float* predict = (const float*)d_in[0];
    const float* score   = (const float*)d_in[1];
    int n  = in_sizes[0];
    int nb = (n + CHUNK - 1) / CHUNK;
    if (nb > MAX_BLOCKS) nb = MAX_BLOCKS;  // (n fixed at 2^24 -> nb = 2048)

    k_count <<<nb, NTHREADS>>>(score, n);
    k_main  <<<nb, NTHREADS>>>(predict, n, nb);
    k_reduce<<<1, 256>>>((float*)d_out, nb);
}

// round 9
// speedup vs baseline: 1.2240x; 1.0049x over previous
#include <cuda_runtime.h>
#include <cuda_bf16.h>

// ---------------------------------------------------------------------------
// NDCG loss, N = 2^24.
// k_count: batched float4 loads (forced MLP=8) -> ballot bitmask + block counts.
// k_scan:  single-block exclusive scan of block counts -> g_pre[], total P.
// k_main:  batched float4 predict loads + MUFU (LG2/RCP) term math.
// k_reduce: fixed-order double sum -> scalar.
// Mask layout: per 128-element tile, words w0..w3; w_d bit t = elem 4t+d.
// ---------------------------------------------------------------------------

#define CHUNK    8192
#define NTHREADS 256
#define NWARPS   (NTHREADS / 32)
#define MAX_TILES  (1 << 18)   // n up to 2^25
#define MAX_BLOCKS 8192

__device__ uint4 g_mask4[MAX_TILES];
__device__ int   g_bcnt[MAX_BLOCKS];
__device__ int   g_pre[MAX_BLOCKS + 1];   // exclusive prefix; g_pre[nb] = total P
__device__ float g_partial[MAX_BLOCKS];

// ---------------------------------------------------------------------------
__global__ __launch_bounds__(NTHREADS)
void k_count(const float* __restrict__ score, int n) {
    int tid  = threadIdx.x;
    int lane = tid & 31;
    int warp = tid >> 5;
    int warpBase = blockIdx.x * CHUNK + warp * 1024;   // 8 tiles of 128

    // Phase A: batch all 8 loads (forces MLP=8 in SASS).
    float4 v[8];
#pragma unroll
    for (int j = 0; j < 8; ++j) {
        int tbase = warpBase + j * 128;
        int myIdx = tbase + lane * 4;
        if (tbase + 128 <= n) {
            v[j] = *reinterpret_cast<const float4*>(score + myIdx);
        } else {
            v[j].x = (myIdx + 0 < n) ? score[myIdx + 0] : 0.0f;
            v[j].y = (myIdx + 1 < n) ? score[myIdx + 1] : 0.0f;
            v[j].z = (myIdx + 2 < n) ? score[myIdx + 2] : 0.0f;
            v[j].w = (myIdx + 3 < n) ? score[myIdx + 3] : 0.0f;
        }
    }
    // Phase B: ballots + mask stores + count.
    int cnt = 0;
#pragma unroll
    for (int j = 0; j < 8; ++j) {
        unsigned w0 = __ballot_sync(0xffffffffu, v[j].x > 0.0f);
        unsigned w1 = __ballot_sync(0xffffffffu, v[j].y > 0.0f);
        unsigned w2 = __ballot_sync(0xffffffffu, v[j].z > 0.0f);
        unsigned w3 = __ballot_sync(0xffffffffu, v[j].w > 0.0f);
        int tbase = warpBase + j * 128;
        if (lane == 0) g_mask4[tbase >> 7] = make_uint4(w0, w1, w2, w3);
        cnt += __popc(w0) + __popc(w1) + __popc(w2) + __popc(w3);
    }
    __shared__ int wc[NWARPS];
    if (lane == 0) wc[warp] = cnt;
    __syncthreads();
    if (tid == 0) {
        int s = 0;
#pragma unroll
        for (int i = 0; i < NWARPS; ++i) s += wc[i];
        g_bcnt[blockIdx.x] = s;
    }
}

// ---------------------------------------------------------------------------
// Single-block exclusive scan of g_bcnt[0..nb) -> g_pre[]; g_pre[nb] = total.
#define SCAN_T 1024
__global__ __launch_bounds__(SCAN_T)
void k_scan(int nb) {
    int tid  = threadIdx.x;
    int lane = tid & 31;
    int warp = tid >> 5;
    int L  = (nb + SCAN_T - 1) / SCAN_T;   // contiguous segment per thread (<=8)
    int s0 = tid * L;
    int local[8];
    int sum = 0;
    for (int i = 0; i < L; ++i) {
        int idx = s0 + i;
        int c = (idx < nb) ? g_bcnt[idx] : 0;
        local[i] = sum;        // exclusive within segment
        sum += c;
    }
    // inclusive warp scan of segment sums
    int inc = sum;
#pragma unroll
    for (int o = 1; o < 32; o <<= 1) {
        int t = __shfl_up_sync(0xffffffffu, inc, o);
        if (lane >= o) inc += t;
    }
    __shared__ int ws[32];
    if (lane == 31) ws[warp] = inc;
    __syncthreads();
    if (warp == 0) {
        int vv = ws[lane];
#pragma unroll
        for (int o = 1; o < 32; o <<= 1) {
            int t = __shfl_up_sync(0xffffffffu, vv, o);
            if (lane >= o) vv += t;
        }
        ws[lane] = vv;
    }
    __syncthreads();
    int excl = inc - sum + (warp ? ws[warp - 1] : 0);
    for (int i = 0; i < L; ++i) {
        int idx = s0 + i;
        if (idx < nb) g_pre[idx] = excl + local[i];
    }
    if (tid == SCAN_T - 1) g_pre[nb] = excl + sum;
}

// ---------------------------------------------------------------------------
// pos: (p/(k+1) - s/log2(k+1))^2 via num=p*l - s*(k+1), den=(k+1)*l.
// neg: (p/(P+m+1))^2, m = idx+1-kinc.  MUFU: 1 LG2 + 1 RCP; one I2F.
__device__ __forceinline__ float term(float praw, int kinc, int pos, int idx,
                                      float inv_sum_s, float s_val, int P) {
    float p  = praw * inv_sum_s;
    int   di = pos ? (kinc + 1) : (P + idx + 2 - kinc);
    float fd = (float)di;
    float l  = __log2f(fd);
    float num = pos ? fmaf(-s_val, fd, p * l) : p;
    float den = pos ? fd * l : fd;
    return __fdividef(num, den);
}

__global__ __launch_bounds__(NTHREADS)
void k_main(const float* __restrict__ predict, int n, int nblocks) {
    int tid  = threadIdx.x;
    int lane = tid & 31;
    int warp = tid >> 5;
    int b    = blockIdx.x;

    // ---- globals from scan (broadcast loads; no block-level work) ----
    const int P    = g_pre[nblocks];
    int kbase      = g_pre[b];
    const float fS        = (float)P;       // S == P exactly (0/1 scores)
    const float s_val     = 1.0f / fS;
    const float sum_s     = fS * s_val;     // ~= jnp.sum(s)
    const float inv_sum_s = 1.0f / sum_s;

    // ---- this warp's 32 mask words (8 tiles x 4) + per-warp k offsets ----
    int base     = b * CHUNK;
    int warpBase = base + warp * 1024;
    const unsigned* g_words = reinterpret_cast<const unsigned*>(g_mask4);
    unsigned myword = g_words[(base >> 5) + warp * 32 + lane];
    int wtot = __popc(myword);
#pragma unroll
    for (int o = 16; o; o >>= 1) wtot += __shfl_xor_sync(0xffffffffu, wtot, o);
    __shared__ int s_wc[NWARPS];
    if (lane == 0) s_wc[warp] = wtot;
    __syncthreads();
#pragma unroll
    for (int i = 0; i < NWARPS; ++i)
        if (i < warp) kbase += s_wc[i];

    // ---- batch all 8 predict loads (MLP=8) ----
    float4 pv[8];
#pragma unroll
    for (int j = 0; j < 8; ++j) {
        int tbase = warpBase + j * 128;
        int myIdx = tbase + lane * 4;
        if (tbase + 128 <= n) {
            pv[j] = *reinterpret_cast<const float4*>(predict + myIdx);
        } else {
            pv[j].x = (myIdx + 0 < n) ? predict[myIdx + 0] : 0.0f;
            pv[j].y = (myIdx + 1 < n) ? predict[myIdx + 1] : 0.0f;
            pv[j].z = (myIdx + 2 < n) ? predict[myIdx + 2] : 0.0f;
            pv[j].w = (myIdx + 3 < n) ? predict[myIdx + 3] : 0.0f;
        }
    }

    // ---- compute terms, 128 elements per warp-iter ----
    const unsigned lt = (1u << lane) - 1u;
    float acc = 0.0f;
#pragma unroll
    for (int j = 0; j < 8; ++j) {
        unsigned w0 = __shfl_sync(0xffffffffu, myword, 4 * j + 0);
        unsigned w1 = __shfl_sync(0xffffffffu, myword, 4 * j + 1);
        unsigned w2 = __shfl_sync(0xffffffffu, myword, 4 * j + 2);
        unsigned w3 = __shfl_sync(0xffffffffu, myword, 4 * j + 3);
        int myIdx = warpBase + j * 128 + lane * 4;
        int pre4 = __popc(w0 & lt) + __popc(w1 & lt)
                 + __popc(w2 & lt) + __popc(w3 & lt);
        int b0 = (w0 >> lane) & 1;
        int b1 = (w1 >> lane) & 1;
        int b2 = (w2 >> lane) & 1;
        int b3 = (w3 >> lane) & 1;
        int k0 = kbase + pre4 + b0;
        int k1 = k0 + b1;
        int k2 = k1 + b2;
        int k3 = k2 + b3;
        float t0 = term(pv[j].x, k0, b0, myIdx + 0, inv_sum_s, s_val, P);
        float t1 = term(pv[j].y, k1, b1, myIdx + 1, inv_sum_s, s_val, P);
        float t2 = term(pv[j].z, k2, b2, myIdx + 2, inv_sum_s, s_val, P);
        float t3 = term(pv[j].w, k3, b3, myIdx + 3, inv_sum_s, s_val, P);
        acc = fmaf(t0, t0, acc);
        acc = fmaf(t1, t1, acc);
        acc = fmaf(t2, t2, acc);
        acc = fmaf(t3, t3, acc);
        kbase += __popc(w0) + __popc(w1) + __popc(w2) + __popc(w3);
    }

    // ---- block reduce ----
#pragma unroll
    for (int o = 16; o; o >>= 1) acc += __shfl_xor_sync(0xffffffffu, acc, o);
    __shared__ float s_acc[NWARPS];
    if (lane == 0) s_acc[warp] = acc;
    __syncthreads();
    if (tid == 0) {
        float s = 0.0f;
#pragma unroll
        for (int i = 0; i < NWARPS; ++i) s += s_acc[i];
        g_partial[b] = s;
    }
}

__global__ __launch_bounds__(256)
void k_reduce(float* __restrict__ out, int nblocks) {
    int tid = threadIdx.x;
    double s = 0.0;
    for (int i = tid; i < nblocks; i += 256) s += (double)g_partial[i];
#pragma unroll
    for (int o = 16; o; o >>= 1) s += __shfl_down_sync(0xffffffffu, s, o);
    __shared__ double sd[8];
    if ((tid & 31) == 0) sd[tid >> 5] = s;
    __syncthreads();
    if (tid == 0) {
        double t = 0.0;
#pragma unroll
        for (int i = 0; i < 8; ++i) t += sd[i];
        out[0] = (float)t;
    }
}

extern "C" void kernel_launch(void* const* d_in, const int* in_sizes, int n_in,
                              void* d_out, int out_size) {
    const float* predict = (const float*)d_in[0];
    const float* score   = (const float*)d_in[1];
    int n  = in_sizes[0];
    int nb = (n + CHUNK - 1) / CHUNK;
    if (nb > MAX_BLOCKS) nb = MAX_BLOCKS;  // (n fixed at 2^24 -> nb = 2048)

    k_count <<<nb, NTHREADS>>>(score, n);
    k_scan  <<<1, SCAN_T>>>(nb);
    k_main  <<<nb, NTHREADS>>>(predict, n, nb);
    k_reduce<<<1, 256>>>((float*)d_out, nb);
}